// round 1
// baseline (speedup 1.0000x reference)
#include <cuda_runtime.h>
#include <stdint.h>

#define BATCH 64
#define HH 1024
#define WW 1024
#define HWSZ (HH*WW)
#define NBINS 4096          // top 12 bits of monotonic float key
#define CAP 4096            // per-batch candidate buffer
#define KMAX 256
#define NMS_R 0.05f

// scratch (no dynamic allocation allowed)
__device__ int g_hist[BATCH * NBINS];
__device__ int g_thresh[BATCH];
__device__ int g_count[BATCH];
__device__ unsigned long long g_cand[BATCH * CAP];

__device__ __forceinline__ unsigned int fkey(float x) {
    unsigned int u = __float_as_uint(x);
    return (u & 0x80000000u) ? ~u : (u | 0x80000000u);  // monotonic: bigger float -> bigger key
}

__global__ void k_zero() {
    int i = blockIdx.x * blockDim.x + threadIdx.x;
    if (i < BATCH * NBINS) g_hist[i] = 0;
}

// 4096 elements per block, 256 threads, float4 loads. One batch per block chunk.
__global__ void k_hist(const float* __restrict__ hm) {
    __shared__ int sh[NBINS];
    for (int i = threadIdx.x; i < NBINS; i += 256) sh[i] = 0;
    __syncthreads();
    const long long base = (long long)blockIdx.x * 4096;
    const int b = (int)(base >> 20);
    const float4* p = (const float4*)(hm + base);
#pragma unroll
    for (int it = 0; it < 4; it++) {
        float4 v = p[threadIdx.x + it * 256];
        atomicAdd(&sh[fkey(v.x) >> 20], 1);
        atomicAdd(&sh[fkey(v.y) >> 20], 1);
        atomicAdd(&sh[fkey(v.z) >> 20], 1);
        atomicAdd(&sh[fkey(v.w) >> 20], 1);
    }
    __syncthreads();
    for (int i = threadIdx.x; i < NBINS; i += 256) {
        int c = sh[i];
        if (c) atomicAdd(&g_hist[b * NBINS + i], c);
    }
}

// per batch: find bin t so that count(bin >= t) >= K; also zero candidate counter
__global__ void k_thresh(const int* __restrict__ ncp) {
    int b = blockIdx.x;
    __shared__ int seg[256];
    int base = threadIdx.x * 16;
    int s = 0;
#pragma unroll
    for (int j = 0; j < 16; j++) s += g_hist[b * NBINS + base + j];
    seg[threadIdx.x] = s;
    __syncthreads();
    if (threadIdx.x == 0) {
        int nc = ncp ? *ncp : 16;
        int K = 4 * nc;
        if (K > KMAX) K = KMAX;
        if (K > HWSZ) K = HWSZ;
        long long acc = 0;
        int t = 0;
        for (int sgi = 255; sgi >= 0; sgi--) {
            if (acc + seg[sgi] >= K) {
                for (int j = 15; j >= 0; j--) {
                    acc += g_hist[b * NBINS + sgi * 16 + j];
                    if (acc >= K) { t = sgi * 16 + j; goto done; }
                }
            }
            acc += seg[sgi];
        }
    done:
        g_thresh[b] = t;
        g_count[b] = 0;
    }
}

__device__ __forceinline__ void try_emit(float x, long long e, int b, unsigned int t) {
    unsigned int kx = fkey(x);
    if ((kx >> 20) >= t) {
        int s = atomicAdd(&g_count[b], 1);
        if (s < CAP) {
            unsigned int pos = (unsigned int)(e & (HWSZ - 1));
            // key: value (monotonic) major, ~pos minor -> ties prefer smaller index
            g_cand[b * CAP + s] = ((unsigned long long)kx << 32) | (unsigned int)(~pos);
        }
    }
}

__global__ void k_collect(const float* __restrict__ hm) {
    const long long base = (long long)blockIdx.x * 4096;
    const int b = (int)(base >> 20);
    const unsigned int t = (unsigned int)g_thresh[b];
    const float4* p = (const float4*)(hm + base);
#pragma unroll
    for (int it = 0; it < 4; it++) {
        int i = threadIdx.x + it * 256;
        float4 v = p[i];
        long long e = base + 4LL * i;
        try_emit(v.x, e + 0, b, t);
        try_emit(v.y, e + 1, b, t);
        try_emit(v.z, e + 2, b, t);
        try_emit(v.w, e + 3, b, t);
    }
}

// per-batch: bitonic sort candidates descending, take top K, greedy NMS, write out
__global__ void k_final(const int* __restrict__ ncp, float* __restrict__ out) {
    int b = blockIdx.x;
    __shared__ unsigned long long key[CAP];
    __shared__ float2 co[KMAX];
    int c = g_count[b];
    if (c > CAP) c = CAP;
    int nc = ncp ? *ncp : 16;
    int K = 4 * nc;
    if (K > KMAX) K = KMAX;
    if (K > HWSZ) K = HWSZ;

    int P = 1;
    while (P < c) P <<= 1;
    if (P < 2) P = 2;
    for (int i = threadIdx.x; i < P; i += 256)
        key[i] = (i < c) ? g_cand[b * CAP + i] : 0ULL;
    __syncthreads();

    // bitonic sort ascending (padding zeros sink to the front; all real keys > 0)
    for (int len = 2; len <= P; len <<= 1) {
        for (int j = len >> 1; j > 0; j >>= 1) {
            for (int i = threadIdx.x; i < P; i += 256) {
                int ixj = i ^ j;
                if (ixj > i) {
                    bool up = ((i & len) == 0);
                    unsigned long long a = key[i], bb = key[ixj];
                    if ((a > bb) == up) { key[i] = bb; key[ixj] = a; }
                }
            }
            __syncthreads();
        }
    }

    int Keff = (K < c) ? K : c;
    for (int i = threadIdx.x; i < Keff; i += 256) {
        unsigned long long kk = key[P - 1 - i];  // descending order
        unsigned int pos = ~(unsigned int)(kk & 0xFFFFFFFFULL);
        co[i] = make_float2((float)(pos & (WW - 1)) / (float)(WW - 1),
                            (float)(pos >> 10) / (float)(HH - 1));
    }
    __syncthreads();

    if (threadIdx.x == 0) {
        float sx[64], sy[64];
        int keep = (nc > 64) ? 64 : nc;
        int sel = 0;
        for (int i = 0; i < Keff && sel < keep; i++) {
            float x = co[i].x, y = co[i].y;
            bool close = false;
            for (int j = 0; j < sel; j++) {
                float dx = x - sx[j], dy = y - sy[j];
                if (sqrtf(dx * dx + dy * dy) < NMS_R) { close = true; break; }
            }
            if (!close) { sx[sel] = x; sy[sel] = y; sel++; }
        }
        for (int s = 0; s < nc; s++) {
            float ox = (s < sel) ? sx[s] : 0.0f;
            float oy = (s < sel) ? sy[s] : 0.0f;
            out[((long long)b * nc + s) * 2 + 0] = ox;
            out[((long long)b * nc + s) * 2 + 1] = oy;
        }
    }
}

extern "C" void kernel_launch(void* const* d_in, const int* in_sizes, int n_in,
                              void* d_out, int out_size) {
    const float* hm = (const float*)d_in[0];
    const int* ncp = (n_in >= 2) ? (const int*)d_in[1] : nullptr;
    float* out = (float*)d_out;

    k_zero<<<(BATCH * NBINS + 255) / 256, 256>>>();
    k_hist<<<(BATCH * (long long)HWSZ) / 4096, 256>>>(hm);
    k_thresh<<<BATCH, 256>>>(ncp);
    k_collect<<<(BATCH * (long long)HWSZ) / 4096, 256>>>(hm);
    k_final<<<BATCH, 256>>>(ncp, out);
    (void)in_sizes; (void)out_size;
}

// round 2
// speedup vs baseline: 1.6198x; 1.6198x over previous
#include <cuda_runtime.h>
#include <stdint.h>

#define BATCH 64
#define HH 1024
#define WW 1024
#define HWSZ (HH*WW)
#define NBINS 4096
#define CAP 4096
#define KMAX 256
#define NMS_R 0.05f
// static threshold: value >= 3.5f  ->  fkey top-12 bits >= 0xC06
#define T12_STATIC 0xC06u

__device__ int g_hist[BATCH * NBINS];
__device__ int g_thresh[BATCH];
__device__ int g_count[BATCH];
__device__ int g_deficit[BATCH];
__device__ int g_anydef;
__device__ unsigned long long g_cand[BATCH * CAP];

__device__ __forceinline__ unsigned int fkey(float x) {
    unsigned int u = __float_as_uint(x);
    return (u & 0x80000000u) ? ~u : (u | 0x80000000u);
}

__global__ void k_zero() {
    int i = blockIdx.x * blockDim.x + threadIdx.x;
    if (i < BATCH * NBINS) g_hist[i] = 0;
    if (i < BATCH) { g_count[i] = 0; g_deficit[i] = 0; }
    if (i == 0) g_anydef = 0;
}

__device__ __forceinline__ void emit(float x, long long e, int b, unsigned int t12) {
    unsigned int kx = fkey(x);
    if ((kx >> 20) >= t12) {
        int s = atomicAdd(&g_count[b], 1);
        if (s < CAP) {
            unsigned int pos = (unsigned int)(e & (HWSZ - 1));
            g_cand[b * CAP + s] = ((unsigned long long)kx << 32) | (unsigned int)(~pos);
        }
    }
}

// fast path: single streaming pass with static threshold. 4096 elems/block.
__global__ void k_collect_static(const float* __restrict__ hm) {
    const long long base = (long long)blockIdx.x * 4096;
    const int b = (int)(base >> 20);
    const float4* p = (const float4*)(hm + base);
#pragma unroll
    for (int it = 0; it < 4; it++) {
        int i = threadIdx.x + it * 256;
        float4 v = p[i];
        long long e = base + 4LL * i;
        emit(v.x, e + 0, b, T12_STATIC);
        emit(v.y, e + 1, b, T12_STATIC);
        emit(v.z, e + 2, b, T12_STATIC);
        emit(v.w, e + 3, b, T12_STATIC);
    }
}

// verify static threshold produced >= K candidates per batch; else flag fallback
__global__ void k_check(const int* __restrict__ ncp) {
    int b = threadIdx.x;
    if (b >= BATCH) return;
    int nc = ncp ? *ncp : 16;
    int K = 4 * nc; if (K > KMAX) K = KMAX; if (K > HWSZ) K = HWSZ;
    if (g_count[b] < K) {
        g_deficit[b] = 1;
        g_count[b] = 0;          // fallback will refill
        atomicExch(&g_anydef, 1);
    }
}

// ---- fallback path (no-op unless some batch was deficient) ----

// grid = BATCH*64 blocks, 16384 elems each
__global__ void fb_hist(const float* __restrict__ hm) {
    const int b = blockIdx.x >> 6;
    if (!g_deficit[b]) return;
    __shared__ int sh[NBINS];
    for (int i = threadIdx.x; i < NBINS; i += 256) sh[i] = 0;
    __syncthreads();
    const long long base = (long long)blockIdx.x * 16384;
    const float4* p = (const float4*)(hm + base);
#pragma unroll
    for (int it = 0; it < 16; it++) {
        float4 v = p[threadIdx.x + it * 256];
        atomicAdd(&sh[fkey(v.x) >> 20], 1);
        atomicAdd(&sh[fkey(v.y) >> 20], 1);
        atomicAdd(&sh[fkey(v.z) >> 20], 1);
        atomicAdd(&sh[fkey(v.w) >> 20], 1);
    }
    __syncthreads();
    for (int i = threadIdx.x; i < NBINS; i += 256) {
        int c = sh[i];
        if (c) atomicAdd(&g_hist[b * NBINS + i], c);
    }
}

__global__ void fb_thresh(const int* __restrict__ ncp) {
    int b = blockIdx.x;
    if (!g_deficit[b]) return;
    __shared__ int seg[256];
    int base = threadIdx.x * 16;
    int s = 0;
#pragma unroll
    for (int j = 0; j < 16; j++) s += g_hist[b * NBINS + base + j];
    seg[threadIdx.x] = s;
    __syncthreads();
    if (threadIdx.x == 0) {
        int nc = ncp ? *ncp : 16;
        int K = 4 * nc; if (K > KMAX) K = KMAX; if (K > HWSZ) K = HWSZ;
        long long acc = 0; int t = 0;
        for (int sgi = 255; sgi >= 0; sgi--) {
            if (acc + seg[sgi] >= K) {
                for (int j = 15; j >= 0; j--) {
                    acc += g_hist[b * NBINS + sgi * 16 + j];
                    if (acc >= K) { t = sgi * 16 + j; goto done; }
                }
            }
            acc += seg[sgi];
        }
    done:
        g_thresh[b] = t;
    }
}

// grid = BATCH*64 blocks, 16384 elems each
__global__ void fb_collect(const float* __restrict__ hm) {
    const int b = blockIdx.x >> 6;
    if (!g_deficit[b]) return;
    const unsigned int t = (unsigned int)g_thresh[b];
    const long long base = (long long)blockIdx.x * 16384;
    const float4* p = (const float4*)(hm + base);
#pragma unroll
    for (int it = 0; it < 16; it++) {
        int i = threadIdx.x + it * 256;
        float4 v = p[i];
        long long e = base + 4LL * i;
        emit(v.x, e + 0, b, t);
        emit(v.y, e + 1, b, t);
        emit(v.z, e + 2, b, t);
        emit(v.w, e + 3, b, t);
    }
}

// ---- final: per-batch bitonic sort + greedy NMS ----
__global__ void k_final(const int* __restrict__ ncp, float* __restrict__ out) {
    int b = blockIdx.x;
    __shared__ unsigned long long key[CAP];
    __shared__ float2 co[KMAX];
    int c = g_count[b];
    if (c > CAP) c = CAP;
    int nc = ncp ? *ncp : 16;
    int K = 4 * nc; if (K > KMAX) K = KMAX; if (K > HWSZ) K = HWSZ;

    int P = 1;
    while (P < c) P <<= 1;
    if (P < 2) P = 2;
    for (int i = threadIdx.x; i < P; i += 256)
        key[i] = (i < c) ? g_cand[b * CAP + i] : 0ULL;
    __syncthreads();

    for (int len = 2; len <= P; len <<= 1) {
        for (int j = len >> 1; j > 0; j >>= 1) {
            for (int i = threadIdx.x; i < P; i += 256) {
                int ixj = i ^ j;
                if (ixj > i) {
                    bool up = ((i & len) == 0);
                    unsigned long long a = key[i], bb = key[ixj];
                    if ((a > bb) == up) { key[i] = bb; key[ixj] = a; }
                }
            }
            __syncthreads();
        }
    }

    int Keff = (K < c) ? K : c;
    for (int i = threadIdx.x; i < Keff; i += 256) {
        unsigned long long kk = key[P - 1 - i];
        unsigned int pos = ~(unsigned int)(kk & 0xFFFFFFFFULL);
        co[i] = make_float2((float)(pos & (WW - 1)) / (float)(WW - 1),
                            (float)(pos >> 10) / (float)(HH - 1));
    }
    __syncthreads();

    if (threadIdx.x == 0) {
        float sx[64], sy[64];
        int keep = (nc > 64) ? 64 : nc;
        int sel = 0;
        for (int i = 0; i < Keff && sel < keep; i++) {
            float x = co[i].x, y = co[i].y;
            bool close = false;
            for (int j = 0; j < sel; j++) {
                float dx = x - sx[j], dy = y - sy[j];
                if (sqrtf(dx * dx + dy * dy) < NMS_R) { close = true; break; }
            }
            if (!close) { sx[sel] = x; sy[sel] = y; sel++; }
        }
        for (int s = 0; s < nc; s++) {
            out[((long long)b * nc + s) * 2 + 0] = (s < sel) ? sx[s] : 0.0f;
            out[((long long)b * nc + s) * 2 + 1] = (s < sel) ? sy[s] : 0.0f;
        }
    }
}

extern "C" void kernel_launch(void* const* d_in, const int* in_sizes, int n_in,
                              void* d_out, int out_size) {
    const float* hm = (const float*)d_in[0];
    const int* ncp = (n_in >= 2) ? (const int*)d_in[1] : nullptr;
    float* out = (float*)d_out;

    k_zero<<<(BATCH * NBINS + 255) / 256, 256>>>();
    k_collect_static<<<(BATCH * (long long)HWSZ) / 4096, 256>>>(hm);
    k_check<<<1, 64>>>(ncp);
    fb_hist<<<BATCH * 64, 256>>>(hm);
    fb_thresh<<<BATCH, 256>>>(ncp);
    fb_collect<<<BATCH * 64, 256>>>(hm);
    k_final<<<BATCH, 256>>>(ncp, out);
    (void)in_sizes; (void)out_size;
}

// round 3
// speedup vs baseline: 1.8597x; 1.1481x over previous
#include <cuda_runtime.h>
#include <stdint.h>

#define BATCH 64
#define HH 1024
#define WW 1024
#define HWSZ (HH*WW)
#define NBINS 4096
#define CAP 4096
#define KMAX 256
#define NMS_R 0.05f
// static threshold: value >= 3.5f  ->  fkey top-12 bits >= 0xC06
#define T12_STATIC 0xC06u

__device__ int g_count[BATCH];
__device__ unsigned long long g_cand[BATCH * CAP];

__device__ __forceinline__ unsigned int fkey(float x) {
    unsigned int u = __float_as_uint(x);
    return (u & 0x80000000u) ? ~u : (u | 0x80000000u);
}

__global__ void k_zero() {
    if (threadIdx.x < BATCH) g_count[threadIdx.x] = 0;
}

__device__ __forceinline__ void emit(float x, long long e, int b, unsigned int t12) {
    unsigned int kx = fkey(x);
    if ((kx >> 20) >= t12) {
        int s = atomicAdd(&g_count[b], 1);
        if (s < CAP) {
            unsigned int pos = (unsigned int)(e & (HWSZ - 1));
            g_cand[b * CAP + s] = ((unsigned long long)kx << 32) | (unsigned int)(~pos);
        }
    }
}

// single streaming pass with static threshold. 4096 elems/block, 16384 blocks.
__global__ void k_collect_static(const float* __restrict__ hm) {
    const long long base = (long long)blockIdx.x * 4096;
    const int b = (int)(base >> 20);
    const float4* p = (const float4*)(hm + base);
#pragma unroll
    for (int it = 0; it < 4; it++) {
        int i = threadIdx.x + it * 256;
        float4 v = p[i];
        long long e = base + 4LL * i;
        emit(v.x, e + 0, b, T12_STATIC);
        emit(v.y, e + 1, b, T12_STATIC);
        emit(v.z, e + 2, b, T12_STATIC);
        emit(v.w, e + 3, b, T12_STATIC);
    }
}

// per-batch: (fallback if static threshold failed) + bitonic sort + greedy NMS
__global__ void k_finalize(const float* __restrict__ hm,
                           const int* __restrict__ ncp,
                           float* __restrict__ out) {
    const int b = blockIdx.x;
    __shared__ unsigned long long key[CAP];
    __shared__ float2 co[KMAX];
    __shared__ int sh_hist[NBINS];   // only touched on fallback
    __shared__ unsigned int sh_t12;

    int nc = ncp ? *ncp : 16;
    int K = 4 * nc; if (K > KMAX) K = KMAX; if (K > HWSZ) K = HWSZ;
    int c = g_count[b];

    // ---- fallback: static threshold missed (too few or overflowed) ----
    if (c < K || c > CAP) {
        for (int i = threadIdx.x; i < NBINS; i += 256) sh_hist[i] = 0;
        __syncthreads();
        const float4* p = (const float4*)(hm + (long long)b * HWSZ);
        for (int i = threadIdx.x; i < HWSZ / 4; i += 256) {
            float4 v = p[i];
            atomicAdd(&sh_hist[fkey(v.x) >> 20], 1);
            atomicAdd(&sh_hist[fkey(v.y) >> 20], 1);
            atomicAdd(&sh_hist[fkey(v.z) >> 20], 1);
            atomicAdd(&sh_hist[fkey(v.w) >> 20], 1);
        }
        __syncthreads();
        if (threadIdx.x == 0) {
            long long acc = 0; unsigned int t = 0;
            for (int i = NBINS - 1; i >= 0; i--) {
                acc += sh_hist[i];
                if (acc >= K) { t = (unsigned int)i; break; }
            }
            sh_t12 = t;
            g_count[b] = 0;
        }
        __syncthreads();
        unsigned int t = sh_t12;
        for (int i = threadIdx.x; i < HWSZ / 4; i += 256) {
            float4 v = p[i];
            long long e = 4LL * i;
            emit(v.x, e + 0, b, t);
            emit(v.y, e + 1, b, t);
            emit(v.z, e + 2, b, t);
            emit(v.w, e + 3, b, t);
        }
        __syncthreads();
        c = g_count[b];
        if (c > CAP) c = CAP;
    }

    // ---- load + bitonic sort (ascending; zero padding sinks to front) ----
    int P = 1;
    while (P < c) P <<= 1;
    if (P < 2) P = 2;
    for (int i = threadIdx.x; i < P; i += 256)
        key[i] = (i < c) ? g_cand[b * CAP + i] : 0ULL;
    __syncthreads();

    for (int len = 2; len <= P; len <<= 1) {
        for (int j = len >> 1; j > 0; j >>= 1) {
            for (int i = threadIdx.x; i < P; i += 256) {
                int ixj = i ^ j;
                if (ixj > i) {
                    bool up = ((i & len) == 0);
                    unsigned long long a = key[i], bb = key[ixj];
                    if ((a > bb) == up) { key[i] = bb; key[ixj] = a; }
                }
            }
            __syncthreads();
        }
    }

    int Keff = (K < c) ? K : c;
    for (int i = threadIdx.x; i < Keff; i += 256) {
        unsigned long long kk = key[P - 1 - i];   // descending
        unsigned int pos = ~(unsigned int)(kk & 0xFFFFFFFFULL);
        co[i] = make_float2((float)(pos & (WW - 1)) / (float)(WW - 1),
                            (float)(pos >> 10) / (float)(HH - 1));
    }
    __syncthreads();

    // ---- greedy sequential NMS (exactly reference semantics) ----
    if (threadIdx.x == 0) {
        float sx[64], sy[64];
        int keep = (nc > 64) ? 64 : nc;
        int sel = 0;
        for (int i = 0; i < Keff && sel < keep; i++) {
            float x = co[i].x, y = co[i].y;
            bool close = false;
            for (int j = 0; j < sel; j++) {
                float dx = x - sx[j], dy = y - sy[j];
                if (sqrtf(dx * dx + dy * dy) < NMS_R) { close = true; break; }
            }
            if (!close) { sx[sel] = x; sy[sel] = y; sel++; }
        }
        for (int s = 0; s < nc; s++) {
            out[((long long)b * nc + s) * 2 + 0] = (s < sel) ? sx[s] : 0.0f;
            out[((long long)b * nc + s) * 2 + 1] = (s < sel) ? sy[s] : 0.0f;
        }
    }
}

extern "C" void kernel_launch(void* const* d_in, const int* in_sizes, int n_in,
                              void* d_out, int out_size) {
    const float* hm = (const float*)d_in[0];
    const int* ncp = (n_in >= 2) ? (const int*)d_in[1] : nullptr;
    float* out = (float*)d_out;

    k_zero<<<1, 64>>>();
    k_collect_static<<<(BATCH * (long long)HWSZ) / 4096, 256>>>(hm);
    k_finalize<<<BATCH, 256>>>(hm, ncp, out);
    (void)in_sizes; (void)out_size;
}

// round 4
// speedup vs baseline: 2.0985x; 1.1284x over previous
#include <cuda_runtime.h>
#include <stdint.h>

#define BATCH 64
#define HH 1024
#define WW 1024
#define HWSZ (HH*WW)
#define NBINS 4096
#define CAP 4096
#define KMAX 256
#define NMS_R 0.05f
// static threshold: value >= 3.5f  ->  fkey top-12 bits >= 0xC06
#define T12_STATIC 0xC06u

__device__ int g_count[BATCH];                       // zero-initialized; self-reset each run
__device__ unsigned long long g_cand[BATCH * CAP];

__device__ __forceinline__ unsigned int fkey(float x) {
    unsigned int u = __float_as_uint(x);
    return (u & 0x80000000u) ? ~u : (u | 0x80000000u);
}

__device__ __forceinline__ void emit(float x, long long e, int b, unsigned int t12) {
    unsigned int kx = fkey(x);
    if ((kx >> 20) >= t12) {
        int s = atomicAdd(&g_count[b], 1);
        if (s < CAP) {
            unsigned int pos = (unsigned int)(e & (HWSZ - 1));
            g_cand[b * CAP + s] = ((unsigned long long)kx << 32) | (unsigned int)(~pos);
        }
    }
}

// single streaming pass with static threshold. 4096 elems/block, 16384 blocks.
__global__ void k_collect_static(const float* __restrict__ hm) {
    const long long base = (long long)blockIdx.x * 4096;
    const int b = (int)(base >> 20);
    const float4* p = (const float4*)(hm + base);
#pragma unroll
    for (int it = 0; it < 4; it++) {
        int i = threadIdx.x + it * 256;
        float4 v = p[i];
        long long e = base + 4LL * i;
        emit(v.x, e + 0, b, T12_STATIC);
        emit(v.y, e + 1, b, T12_STATIC);
        emit(v.z, e + 2, b, T12_STATIC);
        emit(v.w, e + 3, b, T12_STATIC);
    }
}

// per-batch: (exact fallback if static threshold failed) + bitonic sort + parallel NMS
__global__ void k_finalize(const float* __restrict__ hm,
                           const int* __restrict__ ncp,
                           float* __restrict__ out) {
    const int b = blockIdx.x;
    __shared__ unsigned long long key[CAP];
    __shared__ float2 co[KMAX];
    __shared__ unsigned long long adj[64];
    __shared__ int sh_hist[NBINS];   // only touched on fallback
    __shared__ unsigned int sh_t12;

    int nc = ncp ? *ncp : 16;
    int K = 4 * nc; if (K > KMAX) K = KMAX; if (K > HWSZ) K = HWSZ;
    int c = g_count[b];

    // ---- fallback: static threshold missed (too few or overflowed) ----
    if (c < K || c > CAP) {
        for (int i = threadIdx.x; i < NBINS; i += 256) sh_hist[i] = 0;
        __syncthreads();
        const float4* p = (const float4*)(hm + (long long)b * HWSZ);
        for (int i = threadIdx.x; i < HWSZ / 4; i += 256) {
            float4 v = p[i];
            atomicAdd(&sh_hist[fkey(v.x) >> 20], 1);
            atomicAdd(&sh_hist[fkey(v.y) >> 20], 1);
            atomicAdd(&sh_hist[fkey(v.z) >> 20], 1);
            atomicAdd(&sh_hist[fkey(v.w) >> 20], 1);
        }
        __syncthreads();
        if (threadIdx.x == 0) {
            long long acc = 0; unsigned int t = 0;
            for (int i = NBINS - 1; i >= 0; i--) {
                acc += sh_hist[i];
                if (acc >= K) { t = (unsigned int)i; break; }
            }
            sh_t12 = t;
            g_count[b] = 0;
        }
        __syncthreads();
        unsigned int t = sh_t12;
        for (int i = threadIdx.x; i < HWSZ / 4; i += 256) {
            float4 v = p[i];
            long long e = 4LL * i;
            emit(v.x, e + 0, b, t);
            emit(v.y, e + 1, b, t);
            emit(v.z, e + 2, b, t);
            emit(v.w, e + 3, b, t);
        }
        __syncthreads();
        c = g_count[b];
        if (c > CAP) c = CAP;
    }

    // ---- load + bitonic sort (ascending; zero padding sinks to front) ----
    int P = 1;
    while (P < c) P <<= 1;
    if (P < 2) P = 2;
    for (int i = threadIdx.x; i < P; i += 256)
        key[i] = (i < c) ? g_cand[b * CAP + i] : 0ULL;
    __syncthreads();

    for (int len = 2; len <= P; len <<= 1) {
        for (int j = len >> 1; j > 0; j >>= 1) {
            for (int i = threadIdx.x; i < P; i += 256) {
                int ixj = i ^ j;
                if (ixj > i) {
                    bool up = ((i & len) == 0);
                    unsigned long long a = key[i], bb = key[ixj];
                    if ((a > bb) == up) { key[i] = bb; key[ixj] = a; }
                }
            }
            __syncthreads();
        }
    }

    int Keff = (K < c) ? K : c;
    for (int i = threadIdx.x; i < Keff; i += 256) {
        unsigned long long kk = key[P - 1 - i];   // descending
        unsigned int pos = ~(unsigned int)(kk & 0xFFFFFFFFULL);
        co[i] = make_float2((float)(pos & (WW - 1)) / (float)(WW - 1),
                            (float)(pos >> 10) / (float)(HH - 1));
    }
    __syncthreads();

    // ---- greedy NMS ----
    int keep = (nc > 64) ? 64 : nc;
    if (Keff <= 64) {
        // parallel adjacency: thread i -> bitmask of j<i with dist < r
        if (threadIdx.x < (unsigned)Keff) {
            int i = threadIdx.x;
            float x = co[i].x, y = co[i].y;
            unsigned long long m = 0;
            for (int j = 0; j < i; j++) {
                float dx = x - co[j].x, dy = y - co[j].y;
                if (sqrtf(dx * dx + dy * dy) < NMS_R) m |= (1ULL << j);
            }
            adj[i] = m;
        }
        __syncthreads();
        if (threadIdx.x == 0) {
            unsigned long long selmask = 0;
            int sel = 0;
            int order[64];
            for (int i = 0; i < Keff && sel < keep; i++) {
                if ((adj[i] & selmask) == 0) {
                    selmask |= (1ULL << i);
                    order[sel++] = i;
                }
            }
            for (int s = 0; s < nc; s++) {
                float ox = 0.0f, oy = 0.0f;
                if (s < sel) { ox = co[order[s]].x; oy = co[order[s]].y; }
                out[((long long)b * nc + s) * 2 + 0] = ox;
                out[((long long)b * nc + s) * 2 + 1] = oy;
            }
            g_count[b] = 0;   // self-reset for next graph replay
        }
    } else {
        // general serial path (Keff > 64)
        if (threadIdx.x == 0) {
            float sx[64], sy[64];
            int sel = 0;
            for (int i = 0; i < Keff && sel < keep; i++) {
                float x = co[i].x, y = co[i].y;
                bool close = false;
                for (int j = 0; j < sel; j++) {
                    float dx = x - sx[j], dy = y - sy[j];
                    if (sqrtf(dx * dx + dy * dy) < NMS_R) { close = true; break; }
                }
                if (!close) { sx[sel] = x; sy[sel] = y; sel++; }
            }
            for (int s = 0; s < nc; s++) {
                out[((long long)b * nc + s) * 2 + 0] = (s < sel) ? sx[s] : 0.0f;
                out[((long long)b * nc + s) * 2 + 1] = (s < sel) ? sy[s] : 0.0f;
            }
            g_count[b] = 0;   // self-reset for next graph replay
        }
    }
}

extern "C" void kernel_launch(void* const* d_in, const int* in_sizes, int n_in,
                              void* d_out, int out_size) {
    const float* hm = (const float*)d_in[0];
    const int* ncp = (n_in >= 2) ? (const int*)d_in[1] : nullptr;
    float* out = (float*)d_out;

    k_collect_static<<<(BATCH * (long long)HWSZ) / 4096, 256>>>(hm);
    k_finalize<<<BATCH, 256>>>(hm, ncp, out);
    (void)in_sizes; (void)out_size;
}